// round 9
// baseline (speedup 1.0000x reference)
#include <cuda_runtime.h>

// Problem constants
#define IN_DIM  8192
#define OUT_DIM 8192

// Partial-kernel tiling: 256 threads x float4 = 1024 cols/block, 128 row chunks
#define P_THREADS 256
#define VEC 4
#define COLS_PER_BLOCK (P_THREADS * VEC)            // 1024
#define N_STRIPES      (OUT_DIM / COLS_PER_BLOCK)   // 8
#define N_ROW_CHUNKS   128
#define ROWS_PER_CHUNK (IN_DIM / N_ROW_CHUNKS)      // 64

// Init: seed both output halves with bias (out is poisoned each replay)
#define I_THREADS 256
__global__ __launch_bounds__(I_THREADS)
void ibp_init_kernel(const float* __restrict__ bias,
                     float* __restrict__ out) {
    const int i = blockIdx.x * I_THREADS + threadIdx.x;   // [0, 2048) float4s
    float4 b = reinterpret_cast<const float4*>(bias)[i];
    reinterpret_cast<float4*>(out)[i] = b;                // bound_l base
    reinterpret_cast<float4*>(out + OUT_DIM)[i] = b;      // bound_u base
}

__device__ __forceinline__ void red_add_v4(float* p, float x, float y, float z, float w) {
    asm volatile("red.global.add.v4.f32 [%0], {%1, %2, %3, %4};"
                 :: "l"(p), "f"(x), "f"(y), "f"(z), "f"(w) : "memory");
}

__global__ __launch_bounds__(P_THREADS)
void ibp_partial_kernel(const float* __restrict__ l,
                        const float* __restrict__ u,
                        const float* __restrict__ w,
                        float* __restrict__ out) {
    __shared__ float sc[ROWS_PER_CHUNK];
    __shared__ float sr[ROWS_PER_CHUNK];

    const int col0 = blockIdx.x * COLS_PER_BLOCK + threadIdx.x * VEC;
    const int row0 = blockIdx.y * ROWS_PER_CHUNK;

    if (threadIdx.x < ROWS_PER_CHUNK) {
        int i = threadIdx.x;
        float lv = l[row0 + i];
        float uv = u[row0 + i];
        sc[i] = 0.5f * (lv + uv);
        sr[i] = 0.5f * (uv - lv);
    }
    __syncthreads();

    float s1x = 0.f, s1y = 0.f, s1z = 0.f, s1w = 0.f;
    float s2x = 0.f, s2y = 0.f, s2z = 0.f, s2w = 0.f;

    const float4* __restrict__ wp =
        reinterpret_cast<const float4*>(w + (size_t)row0 * OUT_DIM + col0);
    const size_t rstride = OUT_DIM / 4;

    #pragma unroll 8
    for (int i = 0; i < ROWS_PER_CHUNK; i++) {
        float4 wv = __ldcs(&wp[(size_t)i * rstride]);   // stream, evict-first
        float c = sc[i];
        float r = sr[i];
        s1x = fmaf(c, wv.x, s1x);
        s1y = fmaf(c, wv.y, s1y);
        s1z = fmaf(c, wv.z, s1z);
        s1w = fmaf(c, wv.w, s1w);
        s2x = fmaf(r, fabsf(wv.x), s2x);
        s2y = fmaf(r, fabsf(wv.y), s2y);
        s2z = fmaf(r, fabsf(wv.z), s2z);
        s2w = fmaf(r, fabsf(wv.w), s2w);
    }

    // Accumulate directly into the (bias-seeded, L2-resident) outputs.
    red_add_v4(out + col0,           s1x - s2x, s1y - s2y, s1z - s2z, s1w - s2w); // bound_l
    red_add_v4(out + OUT_DIM + col0, s1x + s2x, s1y + s2y, s1z + s2z, s1w + s2w); // bound_u
}

extern "C" void kernel_launch(void* const* d_in, const int* in_sizes, int n_in,
                              void* d_out, int out_size) {
    const float* l    = (const float*)d_in[0];
    const float* u    = (const float*)d_in[1];
    const float* w    = (const float*)d_in[2];
    const float* bias = (const float*)d_in[3];
    float* out = (float*)d_out;

    ibp_init_kernel<<<(OUT_DIM / 4) / I_THREADS, I_THREADS>>>(bias, out);  // 8 CTAs
    dim3 grid(N_STRIPES, N_ROW_CHUNKS);   // (8, 128) = 1024 CTAs x 8 warps
    ibp_partial_kernel<<<grid, P_THREADS>>>(l, u, w, out);
}

// round 11
// speedup vs baseline: 1.1472x; 1.1472x over previous
#include <cuda_runtime.h>

// Problem constants
#define IN_DIM  8192
#define OUT_DIM 8192

// Partial-kernel tiling: 128 threads x float2 = 256 cols/block, 128 row chunks
#define P_THREADS 128
#define VEC 2
#define COLS_PER_BLOCK (P_THREADS * VEC)            // 256
#define N_STRIPES      (OUT_DIM / COLS_PER_BLOCK)   // 32
#define N_ROW_CHUNKS   128
#define ROWS_PER_CHUNK (IN_DIM / N_ROW_CHUNKS)      // 64

// Init: seed both output halves with bias (out is poisoned each replay)
#define I_THREADS 256
__global__ __launch_bounds__(I_THREADS)
void ibp_init_kernel(const float* __restrict__ bias,
                     float* __restrict__ out) {
    const int i = blockIdx.x * I_THREADS + threadIdx.x;   // [0, 2048) float4s
    float4 b = reinterpret_cast<const float4*>(bias)[i];
    reinterpret_cast<float4*>(out)[i] = b;                // bound_l base
    reinterpret_cast<float4*>(out + OUT_DIM)[i] = b;      // bound_u base
}

__device__ __forceinline__ void red_add_v2(float* p, float x, float y) {
    asm volatile("red.global.add.v2.f32 [%0], {%1, %2};"
                 :: "l"(p), "f"(x), "f"(y) : "memory");
}

__global__ __launch_bounds__(P_THREADS)
void ibp_partial_kernel(const float* __restrict__ l,
                        const float* __restrict__ u,
                        const float* __restrict__ w,
                        float* __restrict__ out) {
    __shared__ float sc[ROWS_PER_CHUNK];
    __shared__ float sr[ROWS_PER_CHUNK];

    const int col0 = blockIdx.x * COLS_PER_BLOCK + threadIdx.x * VEC;
    const int row0 = blockIdx.y * ROWS_PER_CHUNK;

    if (threadIdx.x < ROWS_PER_CHUNK) {
        int i = threadIdx.x;
        float lv = l[row0 + i];
        float uv = u[row0 + i];
        sc[i] = 0.5f * (lv + uv);
        sr[i] = 0.5f * (uv - lv);
    }
    __syncthreads();

    float s1x = 0.f, s1y = 0.f;
    float s2x = 0.f, s2y = 0.f;

    const float2* __restrict__ wp =
        reinterpret_cast<const float2*>(w + (size_t)row0 * OUT_DIM + col0);
    const size_t rstride = OUT_DIM / 2;

    #pragma unroll 16
    for (int i = 0; i < ROWS_PER_CHUNK; i++) {
        float2 wv = __ldcs(&wp[(size_t)i * rstride]);   // stream, evict-first
        float c = sc[i];
        float r = sr[i];
        s1x = fmaf(c, wv.x, s1x);
        s1y = fmaf(c, wv.y, s1y);
        s2x = fmaf(r, fabsf(wv.x), s2x);
        s2y = fmaf(r, fabsf(wv.y), s2y);
    }

    // Accumulate directly into the (bias-seeded, L2-resident) outputs.
    red_add_v2(out + col0,           s1x - s2x, s1y - s2y);   // bound_l
    red_add_v2(out + OUT_DIM + col0, s1x + s2x, s1y + s2y);   // bound_u
}

extern "C" void kernel_launch(void* const* d_in, const int* in_sizes, int n_in,
                              void* d_out, int out_size) {
    const float* l    = (const float*)d_in[0];
    const float* u    = (const float*)d_in[1];
    const float* w    = (const float*)d_in[2];
    const float* bias = (const float*)d_in[3];
    float* out = (float*)d_out;

    ibp_init_kernel<<<(OUT_DIM / 4) / I_THREADS, I_THREADS>>>(bias, out);  // 8 CTAs
    dim3 grid(N_STRIPES, N_ROW_CHUNKS);   // (32, 128) = 4096 CTAs x 4 warps
    ibp_partial_kernel<<<grid, P_THREADS>>>(l, u, w, out);
}